// round 17
// baseline (speedup 1.0000x reference)
#include <cuda_runtime.h>
#include <cstdint>

#define NTOK 768
#define LDIM 8
#define HDIM 64
#define NROWS (NTOK*LDIM)          // 6144
#define HOUT_ELEMS (NROWS*HDIM)    // 393216
#define COUT_OFF HOUT_ELEMS

#define TI 32
#define TJ 32
#define JSPLIT 3
#define TPS 8                      // tiles per split (24 total / 3)
#define NIT (NTOK/TI)              // 24
#define SLOTS (NIT*LDIM*JSPLIT)    // 576
#define VW 80

// -------- scratch (no allocations allowed) --------
__device__ float g_q[NROWS*HDIM];
__device__ float g_k[NROWS*HDIM];
__device__ float g_v[NROWS*HDIM];
__device__ float g_cmv[NROWS*4];
__device__ float g_cmvc[NROWS*12];
__device__ float g_acc[SLOTS*VW*TI];   // [slot][d][row] for coalescing
__device__ float g_mx[SLOTS*TI];
__device__ float g_sm[SLOTS*TI];
__device__ unsigned int g_cnt[NIT*LDIM];   // last-block tickets (self-resetting)

using u64 = unsigned long long;

__device__ __forceinline__ u64 ffma2(u64 a, u64 b, u64 c) {
    u64 d; asm("fma.rn.f32x2 %0, %1, %2, %3;" : "=l"(d) : "l"(a), "l"(b), "l"(c)); return d;
}
__device__ __forceinline__ u64 mul2(u64 a, u64 b) {
    u64 d; asm("mul.rn.f32x2 %0, %1, %2;" : "=l"(d) : "l"(a), "l"(b)); return d;
}
__device__ __forceinline__ u64 pack2(float x, float y) {
    u64 r; asm("mov.b64 %0, {%1, %2};" : "=l"(r) : "f"(x), "f"(y)); return r;
}
__device__ __forceinline__ float2 unpk(u64 v) {
    float2 f; asm("mov.b64 {%0, %1}, %2;" : "=f"(f.x), "=f"(f.y) : "l"(v)); return f;
}

__device__ __forceinline__ void cp16(uint32_t s, const void* g) {
    asm volatile("cp.async.cg.shared.global [%0], [%1], 16;" :: "r"(s), "l"(g));
}
#define CP_COMMIT() asm volatile("cp.async.commit_group;" ::: "memory")
#define CP_WAIT(n)  asm volatile("cp.async.wait_group %0;" :: "n"(n) : "memory")

// ==================== Kernel A: MLPs v5 (128 thr / 64-row tiles, 3 CTA/SM) ====================
#define MROWS 64
#define MTHR 128
#define AST 72     // activation row stride: 64 cols + 4-pad after col 32 + 4 tail
#define WST 68     // weight row stride: 64 outs + 4-pad after out 32

// mlp smem layout (floats)
#define M_BUFA 0
#define M_BUFB (MROWS*AST)            // 4608
#define M_WA   (2*MROWS*AST)          // 9216
#define M_WB   (M_WA + 64*WST)        // 13568
#define M_FLOATS (M_WB + 64*WST)      // 17920
#define M_BYTES (M_FLOATS*4)          // 71680

// async load of a 64x64 weight matrix into padded layout: W[c][o] at c*WST + o + (o>=32?4:0)
__device__ __forceinline__ void cp_wpad(const float* __restrict__ wg, uint32_t sW_s, int tid) {
    #pragma unroll
    for (int i = 0; i < 8; i++) {
        int idx = tid + i*MTHR;              // float4 index 0..1023
        int c = idx >> 4;
        int o = (idx & 15) * 4;
        uint32_t off = (uint32_t)(c*WST + o + (o >= 32 ? 4 : 0)) * 4u;
        cp16(sW_s + off, ((const float4*)wg) + idx);
    }
}

// one 64->64 layer + ReLU for 4 rows per thread (rows r, r+16, r+32, r+48).
__device__ __forceinline__ void layerv2(const float* __restrict__ in, const float* __restrict__ sW,
                                        const float* __restrict__ bg,
                                        float* outs, float* outg,
                                        int r, int o0, int wof, int row0) {
    float4 b0 = *(const float4*)&bg[o0];
    float4 b1 = *(const float4*)&bg[o0 + 4];
    u64 acc[4][4];
    #pragma unroll
    for (int k = 0; k < 4; k++) {
        acc[k][0] = pack2(b0.x, b0.y); acc[k][1] = pack2(b0.z, b0.w);
        acc[k][2] = pack2(b1.x, b1.y); acc[k][3] = pack2(b1.z, b1.w);
    }
    const float* in0 = in + r*AST;
    #pragma unroll
    for (int half = 0; half < 2; half++) {
        int coff = half * 36;                    // activation padded offset
        const float* wrow = sW + half*32*WST + wof;
        const float* ip = in0 + coff;
        #pragma unroll 8
        for (int c2 = 0; c2 < 32; c2++) {
            float h0 = ip[c2];
            float h1 = ip[16*AST + c2];
            float h2 = ip[32*AST + c2];
            float h3 = ip[48*AST + c2];
            ulonglong2 wa = *(const ulonglong2*)(wrow + c2*WST);
            ulonglong2 wb = *(const ulonglong2*)(wrow + c2*WST + 4);
            u64 hh;
            hh = pack2(h0, h0);
            acc[0][0] = ffma2(hh, wa.x, acc[0][0]); acc[0][1] = ffma2(hh, wa.y, acc[0][1]);
            acc[0][2] = ffma2(hh, wb.x, acc[0][2]); acc[0][3] = ffma2(hh, wb.y, acc[0][3]);
            hh = pack2(h1, h1);
            acc[1][0] = ffma2(hh, wa.x, acc[1][0]); acc[1][1] = ffma2(hh, wa.y, acc[1][1]);
            acc[1][2] = ffma2(hh, wb.x, acc[1][2]); acc[1][3] = ffma2(hh, wb.y, acc[1][3]);
            hh = pack2(h2, h2);
            acc[2][0] = ffma2(hh, wa.x, acc[2][0]); acc[2][1] = ffma2(hh, wa.y, acc[2][1]);
            acc[2][2] = ffma2(hh, wb.x, acc[2][2]); acc[2][3] = ffma2(hh, wb.y, acc[2][3]);
            hh = pack2(h3, h3);
            acc[3][0] = ffma2(hh, wa.x, acc[3][0]); acc[3][1] = ffma2(hh, wa.y, acc[3][1]);
            acc[3][2] = ffma2(hh, wb.x, acc[3][2]); acc[3][3] = ffma2(hh, wb.y, acc[3][3]);
        }
    }
    #pragma unroll
    for (int k = 0; k < 4; k++) {
        float2 f0 = unpk(acc[k][0]), f1 = unpk(acc[k][1]);
        float2 f2 = unpk(acc[k][2]), f3 = unpk(acc[k][3]);
        float4 lo = make_float4(fmaxf(f0.x,0.f), fmaxf(f0.y,0.f), fmaxf(f1.x,0.f), fmaxf(f1.y,0.f));
        float4 hi = make_float4(fmaxf(f2.x,0.f), fmaxf(f2.y,0.f), fmaxf(f3.x,0.f), fmaxf(f3.y,0.f));
        int rr = r + 16*k;
        if (outs) {
            float* d = &outs[rr*AST + wof];
            *(float4*)d = lo; *(float4*)(d + 4) = hi;
        }
        if (outg) {
            float* d = &outg[(row0 + rr)*HDIM + o0];
            *(float4*)d = lo; *(float4*)(d + 4) = hi;
        }
    }
}

__global__ __launch_bounds__(MTHR) void mlp_kernel(
    const float* __restrict__ h, const float* __restrict__ coord,
    const float* __restrict__ wq1, const float* __restrict__ bq1,
    const float* __restrict__ wq2, const float* __restrict__ bq2,
    const float* __restrict__ wk1, const float* __restrict__ bk1,
    const float* __restrict__ wk2, const float* __restrict__ bk2,
    const float* __restrict__ wv1, const float* __restrict__ bv1,
    const float* __restrict__ wv2, const float* __restrict__ bv2,
    const float* __restrict__ wc1, const float* __restrict__ bc1,
    const float* __restrict__ wc2)
{
    extern __shared__ float sm[];
    float* bufA = sm + M_BUFA;
    float* bufB = sm + M_BUFB;
    float* sWa  = sm + M_WA;
    float* sWb  = sm + M_WB;

    int tid = threadIdx.x;
    int row0 = blockIdx.x * MROWS;
    int chain = blockIdx.y;
    int r = tid >> 3;                 // 0..15
    int o0 = (tid & 7) * 8;
    int wof = o0 + (o0 >= 32 ? 4 : 0);

    uint32_t bufA_s = (uint32_t)__cvta_generic_to_shared(bufA);
    uint32_t sWa_s  = (uint32_t)__cvta_generic_to_shared(sWa);
    uint32_t sWb_s  = (uint32_t)__cvta_generic_to_shared(sWb);

    const float *w1, *b1, *w2, *b2;
    float* gout;
    if (chain == 0)      { w1 = wq1; b1 = bq1; w2 = wq2; b2 = bq2; gout = g_q; }
    else if (chain == 1) { w1 = wk1; b1 = bk1; w2 = wk2; b2 = bk2; gout = g_k; }
    else                 { w1 = wv1; b1 = bv1; w2 = wv2; b2 = bv2; gout = g_v; }

    // prologue: async W1 + h tile
    cp_wpad(w1, sWa_s, tid);
    #pragma unroll
    for (int k = 0; k < 4; k++) {
        int rr = r + 16*k;
        const float* src = &h[(row0 + rr)*HDIM + o0];
        uint32_t dst = bufA_s + (uint32_t)(rr*AST + wof)*4u;
        cp16(dst, src);
        cp16(dst + 16, src + 4);
    }
    CP_COMMIT();
    CP_WAIT(0);
    __syncthreads();

    // prefetch W2 during layer 1
    cp_wpad(w2, sWb_s, tid); CP_COMMIT();
    layerv2(bufA, sWa, b1, bufB, (float*)0, r, o0, wof, row0);
    CP_WAIT(0);
    __syncthreads();

    if (chain != 2) {
        layerv2(bufB, sWb, b2, (float*)0, gout, r, o0, wof, row0);
        return;
    }

    // chain 2: prefetch wc1 into sWa during layer 2
    cp_wpad(wc1, sWa_s, tid); CP_COMMIT();
    layerv2(bufB, sWb, b2, bufA, gout, r, o0, wof, row0);
    CP_WAIT(0);
    __syncthreads();

    // prefetch wc2 into sWb (compact 64x4 layout) during layer 3
    if (tid < 64) cp16(sWb_s + tid*16u, ((const float4*)wc2) + tid);
    CP_COMMIT();
    layerv2(bufA, sWa, bc1, bufB, (float*)0, r, o0, wof, row0);
    CP_WAIT(0);
    __syncthreads();

    // final: cmv = hidden @ wc2 (64 -> 4), 2 outputs per thread
    {
        int rr = tid >> 1;            // 0..63
        int ob = (tid & 1) * 2;
        float a0 = 0.f, a1 = 0.f;
        const float* inr = &bufB[rr*AST];
        const float* sW = sWb;
        #pragma unroll 8
        for (int c = 0; c < 32; c++) {
            float x = inr[c];
            a0 += x * sW[c*4 + ob];
            a1 += x * sW[c*4 + ob + 1];
        }
        #pragma unroll 8
        for (int c = 32; c < 64; c++) {
            float x = inr[c + 4];
            a0 += x * sW[c*4 + ob];
            a1 += x * sW[c*4 + ob + 1];
        }
        int row = row0 + rr;
        g_cmv[row*4 + ob]     = a0;
        g_cmv[row*4 + ob + 1] = a1;
        #pragma unroll
        for (int t = 0; t < 3; t++) {
            g_cmvc[row*12 + ob*3 + t]     = a0 * coord[row*12 + ob*3 + t];
            g_cmvc[row*12 + (ob+1)*3 + t] = a1 * coord[row*12 + (ob+1)*3 + t];
        }
    }
}

// ==================== Kernel B: flash attention (TJ=32, high occupancy) ====================
#define KSTR 68   // multiple of 4: 16B alignment for float4/cp.async
#define SSTR 33
#define STG 81    // padded stage stride for combine (conflict-free)

#define OQT 0
#define OK  2048                    // qT: 64 cols x 32 rows
#define OV  (OK + TJ*KSTR)          // 4224
#define OS  (OV + TJ*VW)            // 6784
#define OC  (OS + TJ*SSTR)          // 7840
#define OFLAG (OC + TI)             // 7872
#define B1_FLOATS (OFLAG + 1)       // 7873
#define B1_BYTES (B1_FLOATS*4)      // 31492

__device__ __forceinline__ void issue_k_tile(uint32_t kp_s, int jb, int l, int tid) {
    int j = tid >> 3, c0 = (tid & 7) * 8;
    const float* src = &g_k[((jb + j)*LDIM + l)*HDIM + c0];
    uint32_t d = kp_s + (uint32_t)(j*KSTR + c0)*4u;
    cp16(d, src);
    cp16(d + 16, src + 4);
}
__device__ __forceinline__ void issue_v_tile(uint32_t vt_s, int jb, int l, int tid) {
    int j = tid >> 3, c0 = (tid & 7) * 8;
    const float* src = &g_v[((jb + j)*LDIM + l)*HDIM + c0];
    uint32_t d = vt_s + (uint32_t)(j*VW + c0)*4u;
    cp16(d, src);
    cp16(d + 16, src + 4);
    if (tid < TJ) {
        int grow = (jb + tid)*LDIM + l;
        uint32_t dv = vt_s + (uint32_t)(tid*VW + 64)*4u;
        cp16(dv, &g_cmv[grow*4]);
        const float* cc = &g_cmvc[grow*12];
        cp16(dv + 16, cc);
        cp16(dv + 32, cc + 4);
        cp16(dv + 48, cc + 8);
    }
}

__global__ __launch_bounds__(256, 5) void attn_part_kernel(
    const float* __restrict__ hin, const float* __restrict__ coord,
    float* __restrict__ out)
{
    extern __shared__ float smf[];
    float* qT = smf + OQT;
    float* kp = smf + OK;
    float* vt = smf + OV;
    float* S  = smf + OS;
    float* cb = smf + OC;

    int tid = threadIdx.x;
    int it = blockIdx.x, l = blockIdx.y, sp = blockIdx.z;
    int i0 = it * TI;
    int j0 = sp * (TPS*TJ);

    uint32_t kp_s = (uint32_t)__cvta_generic_to_shared(kp);
    uint32_t vt_s = (uint32_t)__cvta_generic_to_shared(vt);

    // prologue: start async loads of tile 0
    issue_k_tile(kp_s, j0, l, tid); CP_COMMIT();
    issue_v_tile(vt_s, j0, l, tid); CP_COMMIT();

    // load q tile transposed: qT[c][r] (overlaps with async loads)
    {
        int r = tid >> 3, c0 = (tid & 7) * 8;
        const float* src = &g_q[((i0 + r)*LDIM + l)*HDIM + c0];
        float4 a = *(const float4*)src;
        float4 b = *(const float4*)(src + 4);
        float v8[8] = {a.x, a.y, a.z, a.w, b.x, b.y, b.z, b.w};
        #pragma unroll
        for (int u = 0; u < 8; u++) qT[(c0 + u)*TI + r] = v8[u];
    }

    int r0 = (tid & 7) * 4, jj = tid >> 3;                      // phase1: 4 rows x 1 j
    int row = tid >> 3, sub = tid & 7;                          // phase2 roles
    int ra = tid & 31, dg = tid >> 5;                           // phase3 roles
    int cbase = (dg < 4) ? dg*12 : 48 + (dg - 4)*8;             // 16B-aligned chunks

    float m_reg = -1e30f, s_reg = 0.f;
    u64 ac[6] = {0, 0, 0, 0, 0, 0};

    for (int t = 0; t < TPS; t++) {
        int jb = j0 + t*TJ;

        CP_WAIT(1);            // K(t) complete (V(t) may still be in flight)
        __syncthreads();

        // ---- phase 1: scores -> S[j][r] (transposed) ----
        {
            u64 a00 = 0, a01 = 0;
            const float* kr0 = &kp[jj*KSTR];
            #pragma unroll
            for (int c4 = 0; c4 < 64; c4 += 4) {
                float4 k0v = *(const float4*)&kr0[c4];
                #pragma unroll
                for (int u = 0; u < 4; u++) {
                    ulonglong2 q = *(const ulonglong2*)&qT[(c4 + u)*TI + r0];
                    float k0s = (&k0v.x)[u];
                    u64 k0 = pack2(k0s, k0s);
                    a00 = ffma2(q.x, k0, a00);
                    a01 = ffma2(q.y, k0, a01);
                }
            }
            float2 f0 = unpk(a00), f1 = unpk(a01);
            S[jj*SSTR + r0]     = f0.x;
            S[jj*SSTR + r0 + 1] = f0.y;
            S[jj*SSTR + r0 + 2] = f1.x;
            S[jj*SSTR + r0 + 3] = f1.y;
        }
        __syncthreads();

        // K buffer free: prefetch K(t+1)
        if (t < TPS-1) { issue_k_tile(kp_s, jb + TJ, l, tid); CP_COMMIT(); }

        // ---- phase 2: online softmax update ----
        {
            float tm = -1e30f;
            #pragma unroll
            for (int j = sub; j < TJ; j += 8) tm = fmaxf(tm, S[j*SSTR + row]);
            #pragma unroll
            for (int w = 4; w >= 1; w >>= 1) tm = fmaxf(tm, __shfl_xor_sync(0xffffffffu, tm, w));
            float newm = fmaxf(m_reg, tm);
            float cc = __expf(m_reg - newm);
            float ts = 0.f;
            #pragma unroll
            for (int j = sub; j < TJ; j += 8) {
                float e = __expf(S[j*SSTR + row] - newm);
                S[j*SSTR + row] = e;
                ts += e;
            }
            #pragma unroll
            for (int w = 4; w >= 1; w >>= 1) ts += __shfl_xor_sync(0xffffffffu, ts, w);
            s_reg = s_reg*cc + ts;
            m_reg = newm;
            if (sub == 0) cb[row] = cc;
        }
        if (t < TPS-1) { CP_WAIT(1); } else { CP_WAIT(0); }   // V(t) complete
        __syncthreads();

        // ---- phase 3: rescale + accumulate p @ [V|cmv|cmvc] ----
        {
            float cc = cb[ra];
            u64 c2 = pack2(cc, cc);
            const float* vb = vt + cbase;
            if (dg < 4) {
                #pragma unroll
                for (int u = 0; u < 6; u++) ac[u] = mul2(ac[u], c2);
                #pragma unroll 4
                for (int j = 0; j < TJ; j++) {
                    float p = S[j*SSTR + ra];
                    u64 p2 = pack2(p, p);
                    const float* vr = vb + j*VW;
                    ulonglong2 v01 = *(const ulonglong2*)(vr);
                    ulonglong2 v23 = *(const ulonglong2*)(vr + 4);
                    ulonglong2 v45 = *(const ulonglong2*)(vr + 8);
                    ac[0] = ffma2(p2, v01.x, ac[0]);
                    ac[1] = ffma2(p2, v01.y, ac[1]);
                    ac[2] = ffma2(p2, v23.x, ac[2]);
                    ac[3] = ffma2(p2, v23.y, ac[3]);
                    ac[4] = ffma2(p2, v45.x, ac[4]);
                    ac[5] = ffma2(p2, v45.y, ac[5]);
                }
            } else {
                #pragma unroll
                for (int u = 0; u < 4; u++) ac[u] = mul2(ac[u], c2);
                #pragma unroll 4
                for (int j = 0; j < TJ; j++) {
                    float p = S[j*SSTR + ra];
                    u64 p2 = pack2(p, p);
                    const float* vr = vb + j*VW;
                    ulonglong2 v01 = *(const ulonglong2*)(vr);
                    ulonglong2 v23 = *(const ulonglong2*)(vr + 4);
                    ac[0] = ffma2(p2, v01.x, ac[0]);
                    ac[1] = ffma2(p2, v01.y, ac[1]);
                    ac[2] = ffma2(p2, v23.x, ac[2]);
                    ac[3] = ffma2(p2, v23.y, ac[3]);
                }
            }
        }
        __syncthreads();

        // V buffer free: prefetch V(t+1)
        if (t < TPS-1) { issue_v_tile(vt_s, jb + TJ, l, tid); CP_COMMIT(); }
    }

    // ---- write partials ----
    int slot = (sp*LDIM + l)*NIT + it;
    if (sub == 0) {
        g_mx[slot*TI + row] = m_reg;
        g_sm[slot*TI + row] = s_reg;
    }
    {
        float* ga = &g_acc[(slot*VW + cbase)*TI + ra];
        if (dg < 4) {
            #pragma unroll
            for (int u = 0; u < 6; u++) {
                float2 f = unpk(ac[u]);
                ga[(u*2    )*TI] = f.x;
                ga[(u*2 + 1)*TI] = f.y;
            }
        } else {
            #pragma unroll
            for (int u = 0; u < 4; u++) {
                float2 f = unpk(ac[u]);
                ga[(u*2    )*TI] = f.x;
                ga[(u*2 + 1)*TI] = f.y;
            }
        }
    }

    // ---- last-block ticket: the final split block for this (it,l) combines ----
    __threadfence();
    __syncthreads();
    if (tid == 0) {
        unsigned int o = atomicAdd(&g_cnt[l*NIT + it], 1u);
        bool last = (o == JSPLIT - 1);
        smf[OFLAG] = last ? 1.f : 0.f;
        if (last) g_cnt[l*NIT + it] = 0;     // reset for next launch/replay
    }
    __syncthreads();
    if (smf[OFLAG] == 0.f) return;

    // ---- fused combine (reuses kp/vt region as stage: 2592 <= 5120 floats) ----
    {
        float* stage = smf + OK;
        int b0 = ((0*LDIM + l)*NIT + it);
        int b1 = ((1*LDIM + l)*NIT + it);
        int b2 = ((2*LDIM + l)*NIT + it);

        float m0 = g_mx[b0*TI + ra], m1 = g_mx[b1*TI + ra], m2 = g_mx[b2*TI + ra];
        float M = fmaxf(m0, fmaxf(m1, m2));
        float w0 = __expf(m0 - M), w1 = __expf(m1 - M), w2 = __expf(m2 - M);
        float denom = g_sm[b0*TI + ra]*w0 + g_sm[b1*TI + ra]*w1 + g_sm[b2*TI + ra]*w2;
        float inv = 1.f / denom;

        const float* a0 = &g_acc[(b0*VW + dg*10)*TI + ra];
        const float* a1 = &g_acc[(b1*VW + dg*10)*TI + ra];
        const float* a2 = &g_acc[(b2*VW + dg*10)*TI + ra];
        float* st = &stage[ra*STG + dg*10];
        #pragma unroll
        for (int u = 0; u < 10; u++)
            st[u] = (a0[u*TI]*w0 + a1[u*TI]*w1 + a2[u*TI]*w2) * inv;
        __syncthreads();

        // h output with residual
        {
            int r = tid >> 3, c0 = (tid & 7) * 8;
            int gi = ((it*TI + r)*LDIM + l)*HDIM + c0;
            const float* sg = &stage[r*STG + c0];
            float4 h0 = *(const float4*)&hin[gi];
            float4 h1 = *(const float4*)&hin[gi + 4];
            *(float4*)&out[gi] =
                make_float4(h0.x + sg[0], h0.y + sg[1], h0.z + sg[2], h0.w + sg[3]);
            *(float4*)&out[gi + 4] =
                make_float4(h1.x + sg[4], h1.y + sg[5], h1.z + sg[6], h1.w + sg[7]);
        }
        // coord output: out = coord*(1+S1[k]) - S2[k][t]
        for (int e = tid; e < TI*12; e += 256) {
            int r = e / 12, idx = e % 12, k = idx / 3;
            float S1 = stage[r*STG + 64 + k];
            float S2 = stage[r*STG + 68 + idx];
            int off = ((it*TI + r)*LDIM + l)*12 + idx;
            out[COUT_OFF + off] = coord[off] * (1.f + S1) - S2;
        }
    }
}

// ==================== launch ====================
extern "C" void kernel_launch(void* const* d_in, const int* in_sizes, int n_in,
                              void* d_out, int out_size) {
    const float* h     = (const float*)d_in[0];
    const float* coord = (const float*)d_in[1];
    const float* wq1 = (const float*)d_in[2];
    const float* bq1 = (const float*)d_in[3];
    const float* wq2 = (const float*)d_in[4];
    const float* bq2 = (const float*)d_in[5];
    const float* wk1 = (const float*)d_in[6];
    const float* bk1 = (const float*)d_in[7];
    const float* wk2 = (const float*)d_in[8];
    const float* bk2 = (const float*)d_in[9];
    const float* wv1 = (const float*)d_in[10];
    const float* bv1 = (const float*)d_in[11];
    const float* wv2 = (const float*)d_in[12];
    const float* bv2 = (const float*)d_in[13];
    const float* wc1 = (const float*)d_in[14];
    const float* bc1 = (const float*)d_in[15];
    const float* wc2 = (const float*)d_in[16];
    float* out = (float*)d_out;

    cudaFuncSetAttribute(mlp_kernel, cudaFuncAttributeMaxDynamicSharedMemorySize, M_BYTES);
    mlp_kernel<<<dim3(NROWS/MROWS, 3), MTHR, M_BYTES>>>(h, coord, wq1, bq1, wq2, bq2,
                                                        wk1, bk1, wk2, bk2, wv1, bv1, wv2, bv2,
                                                        wc1, bc1, wc2);

    cudaFuncSetAttribute(attn_part_kernel, cudaFuncAttributeMaxDynamicSharedMemorySize, B1_BYTES);
    attn_part_kernel<<<dim3(NIT, LDIM, JSPLIT), 256, B1_BYTES>>>(h, coord, out);
}